// round 2
// baseline (speedup 1.0000x reference)
#include <cuda_runtime.h>
#include <math.h>

#define B_ 32
#define D_ 512
#define N_ 2048
#define K_ 64

// Scratch (static device globals -- no allocation allowed). 16B-aligned for float4 access.
__device__ __align__(16) float g_scores[(size_t)B_ * N_ * K_];   // [b][n][k]  16 MB
__device__ __align__(16) float g_ssum[B_ * K_];                  // [b][k]
__device__ __align__(16) float g_agg[(size_t)B_ * D_ * K_];      // [b][d][k]  4 MB
__device__ __align__(16) float g_colss[B_ * K_];                 // [b][k]
__device__ __align__(16) float g_mult[B_ * K_];                  // [b][k]

// ---------------------------------------------------------------------------
__global__ void k_init() {
    int t = blockIdx.x * blockDim.x + threadIdx.x;
    if (t < B_ * K_) { g_ssum[t] = 0.f; g_colss[t] = 0.f; }
}

// ---------------------------------------------------------------------------
// Kernel 1: scores = softmax_K(W @ x_b) for a 64(n) x 64(k) tile; also
// accumulates s_sum[b][k] via atomics. Block = 256 threads, tile K=64 x N=64,
// inner K-dim = D in chunks of 16.
__global__ __launch_bounds__(256) void k_scores(const float* __restrict__ x,
                                                const float* __restrict__ W) {
    const int b  = blockIdx.y;
    const int n0 = blockIdx.x * 64;
    __shared__ float Ws[16][65];   // [dd][k]  (scalar writes, padded reads)
    __shared__ float xs[16][64];   // [dd][nn] (256B rows -> float4 safe)
    __shared__ float sc[64][65];   // [k][nn]  (scalar only)
    const int tid = threadIdx.x;
    const int tx = tid & 15, ty = tid >> 4;

    float c[4][4];
#pragma unroll
    for (int i = 0; i < 4; i++)
#pragma unroll
        for (int j = 0; j < 4; j++) c[i][j] = 0.f;

    for (int d0 = 0; d0 < D_; d0 += 16) {
        {   // load W chunk: 64 k x 16 d
            int k  = tid >> 2;
            int dd = (tid & 3) * 4;
            float4 w4 = *(const float4*)&W[k * D_ + d0 + dd];
            Ws[dd + 0][k] = w4.x; Ws[dd + 1][k] = w4.y;
            Ws[dd + 2][k] = w4.z; Ws[dd + 3][k] = w4.w;
        }
        {   // load x chunk: 16 d x 64 n
            int dd = tid >> 4;
            int nn = (tid & 15) * 4;
            float4 x4 = *(const float4*)&x[(size_t)b * D_ * N_ + (size_t)(d0 + dd) * N_ + n0 + nn];
            *(float4*)&xs[dd][nn] = x4;
        }
        __syncthreads();
#pragma unroll
        for (int dd = 0; dd < 16; dd++) {
            float a[4], bb[4];
#pragma unroll
            for (int i = 0; i < 4; i++) a[i] = Ws[dd][ty + i * 16];
#pragma unroll
            for (int j = 0; j < 4; j++) bb[j] = xs[dd][tx + j * 16];
#pragma unroll
            for (int i = 0; i < 4; i++)
#pragma unroll
                for (int j = 0; j < 4; j++)
                    c[i][j] = fmaf(a[i], bb[j], c[i][j]);
        }
        __syncthreads();
    }

    // stash tile into smem as [k][n]
#pragma unroll
    for (int i = 0; i < 4; i++)
#pragma unroll
        for (int j = 0; j < 4; j++)
            sc[ty + i * 16][tx + j * 16] = c[i][j];
    __syncthreads();

    // softmax over K=64 per column; each warp owns 8 columns, lanes split K in two
    const int lane = tid & 31, wid = tid >> 5;
#pragma unroll
    for (int w = 0; w < 8; w++) {
        int col = wid * 8 + w;
        float v0 = sc[lane][col], v1 = sc[lane + 32][col];
        float m = fmaxf(v0, v1);
#pragma unroll
        for (int o = 16; o > 0; o >>= 1) m = fmaxf(m, __shfl_xor_sync(0xffffffff, m, o));
        float e0 = __expf(v0 - m), e1 = __expf(v1 - m);
        float s = e0 + e1;
#pragma unroll
        for (int o = 16; o > 0; o >>= 1) s += __shfl_xor_sync(0xffffffff, s, o);
        float inv = 1.f / s;
        sc[lane][col]      = e0 * inv;
        sc[lane + 32][col] = e1 * inv;
    }
    __syncthreads();

    // write scores [b][n][k] (coalesced: k fastest)
    float* sptr = &g_scores[(size_t)b * N_ * K_ + (size_t)n0 * K_];
#pragma unroll
    for (int p = 0; p < 16; p++) {
        int idx = tid + p * 256;
        int nn = idx >> 6, k = idx & 63;
        sptr[idx] = sc[k][nn];
    }
    // s_sum partial per k over this n-tile
    if (tid < 64) {
        float s = 0.f;
#pragma unroll
        for (int nn = 0; nn < 64; nn++) s += sc[tid][nn];
        atomicAdd(&g_ssum[b * K_ + tid], s);
    }
}

// ---------------------------------------------------------------------------
// Kernel 2: agg[b][d][k] = sum_n x[b][d][n] * scores[b][n][k]
// Tile: 32(d) x 64(k), K-dim = N in chunks of 32. Block = 256 threads, 2x4 micro.
__global__ __launch_bounds__(256) void k_agg(const float* __restrict__ x) {
    const int b  = blockIdx.y;
    const int d0 = blockIdx.x * 32;
    __shared__ float xs[32][32];  // [dd][nn] 128B rows -> float4 aligned; reads are broadcast
    __shared__ float ss[32][64];  // [nn][k]  256B rows -> float4 aligned
    const int tid = threadIdx.x;
    const int tx = tid & 15, ty = tid >> 4;

    float c[2][4];
#pragma unroll
    for (int i = 0; i < 2; i++)
#pragma unroll
        for (int j = 0; j < 4; j++) c[i][j] = 0.f;

    for (int n0 = 0; n0 < N_; n0 += 32) {
        {   // load x chunk: 32 d x 32 n
            int dd = tid >> 3;
            int nn = (tid & 7) * 4;
            float4 x4 = *(const float4*)&x[(size_t)b * D_ * N_ + (size_t)(d0 + dd) * N_ + n0 + nn];
            *(float4*)&xs[dd][nn] = x4;
        }
        {   // load scores chunk: 32 n x 64 k
            int nn = tid >> 3;
            int k8 = (tid & 7) * 8;
            const float* sp = &g_scores[(size_t)b * N_ * K_ + (size_t)(n0 + nn) * K_ + k8];
            float4 s0 = *(const float4*)sp;
            float4 s1 = *(const float4*)(sp + 4);
            *(float4*)&ss[nn][k8]     = s0;
            *(float4*)&ss[nn][k8 + 4] = s1;
        }
        __syncthreads();
#pragma unroll
        for (int nn = 0; nn < 32; nn++) {
            float a0 = xs[ty][nn], a1 = xs[ty + 16][nn];   // broadcast reads
            float bb[4];
#pragma unroll
            for (int j = 0; j < 4; j++) bb[j] = ss[nn][tx + j * 16];
#pragma unroll
            for (int j = 0; j < 4; j++) {
                c[0][j] = fmaf(a0, bb[j], c[0][j]);
                c[1][j] = fmaf(a1, bb[j], c[1][j]);
            }
        }
        __syncthreads();
    }
    float* ap = &g_agg[(size_t)b * D_ * K_ + (size_t)d0 * K_];
#pragma unroll
    for (int i = 0; i < 2; i++)
#pragma unroll
        for (int j = 0; j < 4; j++)
            ap[(ty + i * 16) * K_ + tx + j * 16] = c[i][j];
}

// ---------------------------------------------------------------------------
// Kernel 3a: per (b, d-tile of 32), accumulate colss[b][k] = sum_d v^2
// where v = agg - centers*ssum.
__global__ __launch_bounds__(256) void k_colss(const float* __restrict__ centers) {
    const int b  = blockIdx.y;
    const int d0 = blockIdx.x * 32;
    const int tid = threadIdx.x;
    const int k = tid & 63, dg = tid >> 6;  // 4 d-groups
    __shared__ float red[4][64];
    const float ssumk = g_ssum[b * K_ + k];
    float acc = 0.f;
#pragma unroll
    for (int t = 0; t < 8; t++) {
        int d = d0 + dg + t * 4;
        float v = g_agg[(size_t)b * D_ * K_ + (size_t)d * K_ + k] - centers[d * K_ + k] * ssumk;
        acc = fmaf(v, v, acc);
    }
    red[dg][k] = acc;
    __syncthreads();
    if (tid < 64) {
        float tot = red[0][tid] + red[1][tid] + red[2][tid] + red[3][tid];
        atomicAdd(&g_colss[b * K_ + tid], tot);
    }
}

// ---------------------------------------------------------------------------
// Kernel 3b: per-batch, compute final per-(b,k) multiplier combining both norms.
__global__ void k_mult() {
    const int b = blockIdx.x;
    const int k = threadIdx.x;  // 64 threads
    __shared__ float sh[64];
    float ss = g_colss[b * K_ + k];
    float m = fmaxf(sqrtf(ss), 1e-12f);
    float after = ss / (m * m);  // sumsq of intranormed column
    sh[k] = after;
    __syncthreads();
    for (int o = 32; o > 0; o >>= 1) {
        if (k < o) sh[k] += sh[k + o];
        __syncthreads();
    }
    float total = sh[0];
    float scale2 = 1.f / fmaxf(sqrtf(total), 1e-12f);
    g_mult[b * K_ + k] = scale2 / m;
}

// ---------------------------------------------------------------------------
// Kernel 3c: out[b][d*K+k] = (agg - centers*ssum) * mult
__global__ __launch_bounds__(256) void k_out(const float* __restrict__ centers,
                                             float* __restrict__ out) {
    const int b  = blockIdx.y;
    const int d0 = blockIdx.x * 32;
    const int tid = threadIdx.x;
    const int k = tid & 63, dg = tid >> 6;
    const float ssumk = g_ssum[b * K_ + k];
    const float mult  = g_mult[b * K_ + k];
    float* op = &out[(size_t)b * D_ * K_];
#pragma unroll
    for (int t = 0; t < 8; t++) {
        int d = d0 + dg + t * 4;
        float v = g_agg[(size_t)b * D_ * K_ + (size_t)d * K_ + k] - centers[d * K_ + k] * ssumk;
        op[d * K_ + k] = v * mult;
    }
}

// ---------------------------------------------------------------------------
extern "C" void kernel_launch(void* const* d_in, const int* in_sizes, int n_in,
                              void* d_out, int out_size) {
    const float* x       = (const float*)d_in[0];  // [B, D, N]
    const float* W       = (const float*)d_in[1];  // [K, D]
    const float* centers = (const float*)d_in[2];  // [D, K]
    float* out = (float*)d_out;                    // [B, D*K]

    k_init<<<8, 256>>>();
    dim3 g1(N_ / 64, B_);
    k_scores<<<g1, 256>>>(x, W);
    dim3 g2(D_ / 32, B_);
    k_agg<<<g2, 256>>>(x);
    k_colss<<<g2, 256>>>(centers);
    k_mult<<<B_, 64>>>();
    k_out<<<g2, 256>>>(centers, out);
}

// round 4
// speedup vs baseline: 2.3667x; 2.3667x over previous
#include <cuda_runtime.h>
#include <cuda_bf16.h>
#include <math.h>
#include <stdint.h>

#define B_ 32
#define D_ 512
#define N_ 2048
#define K_ 64

// ---------------------------------------------------------------------------
// Scratch (static device globals; no allocations allowed)
// g_scores: packed (hi,lo) bf16 per element: word = hi | (lo<<16), layout [b][k][n]
__device__ __align__(16) unsigned g_scores[(size_t)B_ * K_ * N_];  // 16 MB
__device__ __align__(16) float g_ssum[B_ * K_];
__device__ __align__(16) float g_agg[(size_t)B_ * D_ * K_];        // 4 MB, [b][d][k]
__device__ __align__(16) float g_colss[B_ * K_];
__device__ __align__(16) float g_mult[B_ * K_];

// ---------------------------------------------------------------------------
__device__ __forceinline__ uint32_t smem_u32(const void* p) {
    uint32_t a;
    asm("{ .reg .u64 t; cvta.to.shared.u64 t, %1; cvt.u32.u64 %0, t; }" : "=r"(a) : "l"(p));
    return a;
}
__device__ __forceinline__ void ldsm4(uint32_t* r, uint32_t a) {
    asm volatile("ldmatrix.sync.aligned.m8n8.x4.shared.b16 {%0,%1,%2,%3}, [%4];"
                 : "=r"(r[0]), "=r"(r[1]), "=r"(r[2]), "=r"(r[3]) : "r"(a));
}
__device__ __forceinline__ void ldsm4t(uint32_t* r, uint32_t a) {
    asm volatile("ldmatrix.sync.aligned.m8n8.x4.trans.shared.b16 {%0,%1,%2,%3}, [%4];"
                 : "=r"(r[0]), "=r"(r[1]), "=r"(r[2]), "=r"(r[3]) : "r"(a));
}
__device__ __forceinline__ void mma_bf16(float* c, const uint32_t* a, const uint32_t* b) {
    asm volatile("mma.sync.aligned.m16n8k16.row.col.f32.bf16.bf16.f32 "
                 "{%0,%1,%2,%3}, {%4,%5,%6,%7}, {%8,%9}, {%0,%1,%2,%3};"
                 : "+f"(c[0]), "+f"(c[1]), "+f"(c[2]), "+f"(c[3])
                 : "r"(a[0]), "r"(a[1]), "r"(a[2]), "r"(a[3]), "r"(b[0]), "r"(b[1]));
}
// split two floats into packed bf16 hi-pair and lo-pair words
__device__ __forceinline__ void split2(float x, float y, uint32_t& hi, uint32_t& lo) {
    __nv_bfloat16 hx = __float2bfloat16(x), hy = __float2bfloat16(y);
    float rx = x - __bfloat162float(hx), ry = y - __bfloat162float(hy);
    __nv_bfloat16 lx = __float2bfloat16(rx), ly = __float2bfloat16(ry);
    hi = (uint32_t)__bfloat16_as_ushort(hx) | ((uint32_t)__bfloat16_as_ushort(hy) << 16);
    lo = (uint32_t)__bfloat16_as_ushort(lx) | ((uint32_t)__bfloat16_as_ushort(ly) << 16);
}

// ---------------------------------------------------------------------------
__global__ void k_init() {
    int t = blockIdx.x * blockDim.x + threadIdx.x;
    if (t < B_ * K_) { g_ssum[t] = 0.f; g_colss[t] = 0.f; }
    if (t < B_ * D_ * K_) g_agg[t] = 0.f;
}

// ---------------------------------------------------------------------------
// Kernel A: logits[64 k][128 n] = W @ x_tile (reduce D=512), hi/lo 3-pass MMA,
// fused softmax over k, writes packed scores [b][k][n] + partial s_sum.
// Dynamic smem layout:
//   Wh: [64][40] bf16 @0 (5120B)   Wl: @5120
//   Xh: [32][136] bf16 @10240 (8704B)  Xl: @18944   (loop region ends 27648)
//   st: [64][132] f32 @0 (33792B, reused after loop)   ssred: [64] f32 @33792
#define PA 40
#define PX 136
#define A_SMEM (33792 + 256)

__global__ __launch_bounds__(256) void kA(const float* __restrict__ x,
                                          const float* __restrict__ W) {
    extern __shared__ char sm[];
    const int b = blockIdx.y, n0 = blockIdx.x * 128;
    const int tid = threadIdx.x, lane = tid & 31, wid = tid >> 5;
    const int wm = wid & 3, wn = wid >> 2;

    __nv_bfloat16* Wh = (__nv_bfloat16*)(sm);
    __nv_bfloat16* Wl = (__nv_bfloat16*)(sm + 5120);
    __nv_bfloat16* Xh = (__nv_bfloat16*)(sm + 10240);
    __nv_bfloat16* Xl = (__nv_bfloat16*)(sm + 18944);
    const uint32_t wh_a = smem_u32(Wh), wl_a = smem_u32(Wl);
    const uint32_t xh_a = smem_u32(Xh), xl_a = smem_u32(Xl);

    float acc[8][4];
#pragma unroll
    for (int i = 0; i < 8; i++)
#pragma unroll
        for (int j = 0; j < 4; j++) acc[i][j] = 0.f;

    for (int d0 = 0; d0 < D_; d0 += 32) {
        // W chunk [64 k][32 d]: warp reads 4 rows x 128B, fully coalesced
#pragma unroll
        for (int p = 0; p < 2; p++) {
            int k = (tid >> 3) + p * 32;
            int dd = (tid & 7) * 4;
            float4 v = *(const float4*)&W[k * D_ + d0 + dd];
            uint32_t h0, l0, h1, l1;
            split2(v.x, v.y, h0, l0); split2(v.z, v.w, h1, l1);
            int off = k * PA + dd;
            *(uint32_t*)&Wh[off] = h0; *(uint32_t*)&Wh[off + 2] = h1;
            *(uint32_t*)&Wl[off] = l0; *(uint32_t*)&Wl[off + 2] = l1;
        }
        // x chunk [32 d][128 n]: one warp per row (512B), coalesced
#pragma unroll
        for (int p = 0; p < 4; p++) {
            int dd = wid + p * 8;
            int nn = lane * 4;
            float4 v = *(const float4*)&x[((size_t)b * D_ + d0 + dd) * N_ + n0 + nn];
            uint32_t h0, l0, h1, l1;
            split2(v.x, v.y, h0, l0); split2(v.z, v.w, h1, l1);
            int off = dd * PX + nn;
            *(uint32_t*)&Xh[off] = h0; *(uint32_t*)&Xh[off + 2] = h1;
            *(uint32_t*)&Xl[off] = l0; *(uint32_t*)&Xl[off + 2] = l1;
        }
        __syncthreads();

#pragma unroll
        for (int ks = 0; ks < 2; ks++) {
            uint32_t ah[4], al[4];
            uint32_t aoff = (uint32_t)(((wm * 16 + (lane & 15)) * PA + ks * 16 + (lane >> 4) * 8) * 2);
            ldsm4(ah, wh_a + aoff);
            ldsm4(al, wl_a + aoff);
#pragma unroll
            for (int nf = 0; nf < 4; nf++) {
                uint32_t bh[4], bl[4];
                uint32_t boff = (uint32_t)(((ks * 16 + (lane & 15)) * PX +
                                            wn * 64 + nf * 16 + (lane >> 4) * 8) * 2);
                ldsm4t(bh, xh_a + boff);
                ldsm4t(bl, xl_a + boff);
                mma_bf16(acc[nf * 2],     ah, bh);
                mma_bf16(acc[nf * 2],     ah, bl);
                mma_bf16(acc[nf * 2],     al, bh);
                mma_bf16(acc[nf * 2 + 1], ah, bh + 2);
                mma_bf16(acc[nf * 2 + 1], ah, bl + 2);
                mma_bf16(acc[nf * 2 + 1], al, bh + 2);
            }
        }
        __syncthreads();
    }

    // stash logits tile to smem [64][132] f32
    float* st = (float*)sm;
    {
        int g = lane >> 2, tg = lane & 3;
        int r0 = wm * 16 + g;
#pragma unroll
        for (int nf = 0; nf < 8; nf++) {
            int c = wn * 64 + nf * 8 + tg * 2;
            st[r0 * 132 + c]           = acc[nf][0];
            st[r0 * 132 + c + 1]       = acc[nf][1];
            st[(r0 + 8) * 132 + c]     = acc[nf][2];
            st[(r0 + 8) * 132 + c + 1] = acc[nf][3];
        }
    }
    float* ssred = (float*)(sm + 33792);
    if (tid < 64) ssred[tid] = 0.f;
    __syncthreads();

    // softmax over k per column (threads 0..127, one column each)
    if (tid < 128) {
        int col = tid;
        float m = -1e30f;
#pragma unroll
        for (int k = 0; k < 64; k++) m = fmaxf(m, st[k * 132 + col]);
        float s = 0.f;
#pragma unroll
        for (int k = 0; k < 64; k++) s += __expf(st[k * 132 + col] - m);
        float inv = 1.f / s;
        unsigned* sp = &g_scores[((size_t)b * K_) * N_ + n0 + col];
#pragma unroll
        for (int k = 0; k < 64; k++) {
            float v = __expf(st[k * 132 + col] - m) * inv;
            __nv_bfloat16 h = __float2bfloat16(v);
            float r = v - __bfloat162float(h);
            __nv_bfloat16 l = __float2bfloat16(r);
            sp[(size_t)k * N_] = (uint32_t)__bfloat16_as_ushort(h) |
                                 ((uint32_t)__bfloat16_as_ushort(l) << 16);
            float ws = v;
#pragma unroll
            for (int o = 16; o > 0; o >>= 1) ws += __shfl_xor_sync(0xffffffff, ws, o);
            if (lane == 0) atomicAdd(&ssred[k], ws);
        }
    }
    __syncthreads();
    if (tid < 64) atomicAdd(&g_ssum[b * K_ + tid], ssred[tid]);
}

// ---------------------------------------------------------------------------
// Kernel B: agg[128 d][64 k] += x_tile @ scores^T (reduce n in [sp*1024, +1024))
#define PB 40
__global__ __launch_bounds__(256) void kB(const float* __restrict__ x) {
    __shared__ __align__(16) __nv_bfloat16 Xh[128 * PB];
    __shared__ __align__(16) __nv_bfloat16 Xl[128 * PB];
    __shared__ __align__(16) __nv_bfloat16 Sh[64 * PB];
    __shared__ __align__(16) __nv_bfloat16 Sl[64 * PB];
    const int b = blockIdx.y;
    const int d0 = (blockIdx.x & 3) * 128;
    const int spn = (blockIdx.x >> 2) * 1024;
    const int tid = threadIdx.x, lane = tid & 31, wid = tid >> 5;
    const uint32_t xh_a = smem_u32(Xh), xl_a = smem_u32(Xl);
    const uint32_t sh_a = smem_u32(Sh), sl_a = smem_u32(Sl);

    float acc[8][4];
#pragma unroll
    for (int i = 0; i < 8; i++)
#pragma unroll
        for (int j = 0; j < 4; j++) acc[i][j] = 0.f;

    for (int n0 = spn; n0 < spn + 1024; n0 += 32) {
        // x chunk [128 d][32 n]: warp reads 4 rows x 128B coalesced
#pragma unroll
        for (int p = 0; p < 4; p++) {
            int rr = (tid >> 3) + p * 32;
            int nn = (tid & 7) * 4;
            float4 v = *(const float4*)&x[((size_t)b * D_ + d0 + rr) * N_ + n0 + nn];
            uint32_t h0, l0, h1, l1;
            split2(v.x, v.y, h0, l0); split2(v.z, v.w, h1, l1);
            int off = rr * PB + nn;
            *(uint32_t*)&Xh[off] = h0; *(uint32_t*)&Xh[off + 2] = h1;
            *(uint32_t*)&Xl[off] = l0; *(uint32_t*)&Xl[off + 2] = l1;
        }
        // scores chunk [64 k][32 n] packed words; split hi/lo
#pragma unroll
        for (int p = 0; p < 4; p++) {
            int k = (tid >> 4) + p * 16;
            int n2 = (tid & 15) * 2;
            uint2 w = *(const uint2*)&g_scores[((size_t)b * K_ + k) * N_ + n0 + n2];
            int off = k * PB + n2;
            *(uint32_t*)&Sh[off] = __byte_perm(w.x, w.y, 0x5410);
            *(uint32_t*)&Sl[off] = __byte_perm(w.x, w.y, 0x7632);
        }
        __syncthreads();

#pragma unroll
        for (int ks = 0; ks < 2; ks++) {
            uint32_t ah[4], al[4];
            uint32_t aoff = (uint32_t)(((wid * 16 + (lane & 15)) * PB + ks * 16 + (lane >> 4) * 8) * 2);
            ldsm4(ah, xh_a + aoff);
            ldsm4(al, xl_a + aoff);
#pragma unroll
            for (int nf = 0; nf < 4; nf++) {
                uint32_t bh[4], bl[4];
                uint32_t boff = (uint32_t)(((nf * 16 + (lane & 7) + ((lane >> 4) << 3)) * PB +
                                            ks * 16 + ((lane >> 3) & 1) * 8) * 2);
                ldsm4(bh, sh_a + boff);   // non-trans: pairs along n (contiguous)
                ldsm4(bl, sl_a + boff);
                mma_bf16(acc[nf * 2],     ah, bh);
                mma_bf16(acc[nf * 2],     ah, bl);
                mma_bf16(acc[nf * 2],     al, bh);
                mma_bf16(acc[nf * 2 + 1], ah, bh + 2);
                mma_bf16(acc[nf * 2 + 1], ah, bl + 2);
                mma_bf16(acc[nf * 2 + 1], al, bh + 2);
            }
        }
        __syncthreads();
    }

    // accumulate into g_agg[b][d][k]
    int g = lane >> 2, tg = lane & 3;
    int d = d0 + wid * 16 + g;
    float* base = &g_agg[((size_t)b * D_ + d) * K_];
#pragma unroll
    for (int nf = 0; nf < 8; nf++) {
        int c = nf * 8 + tg * 2;
        atomicAdd(&base[c],            acc[nf][0]);
        atomicAdd(&base[c + 1],        acc[nf][1]);
        atomicAdd(&base[8 * K_ + c],       acc[nf][2]);
        atomicAdd(&base[8 * K_ + c + 1],   acc[nf][3]);
    }
}

// ---------------------------------------------------------------------------
// Epilogue (unchanged from passing R2 kernel)
__global__ __launch_bounds__(256) void k_colss(const float* __restrict__ centers) {
    const int b = blockIdx.y, d0 = blockIdx.x * 32;
    const int tid = threadIdx.x;
    const int k = tid & 63, dg = tid >> 6;
    __shared__ float red[4][64];
    const float ssumk = g_ssum[b * K_ + k];
    float acc = 0.f;
#pragma unroll
    for (int t = 0; t < 8; t++) {
        int d = d0 + dg + t * 4;
        float v = g_agg[(size_t)b * D_ * K_ + (size_t)d * K_ + k] - centers[d * K_ + k] * ssumk;
        acc = fmaf(v, v, acc);
    }
    red[dg][k] = acc;
    __syncthreads();
    if (tid < 64) {
        float tot = red[0][tid] + red[1][tid] + red[2][tid] + red[3][tid];
        atomicAdd(&g_colss[b * K_ + tid], tot);
    }
}

__global__ void k_mult() {
    const int b = blockIdx.x, k = threadIdx.x;
    __shared__ float sh[64];
    float ss = g_colss[b * K_ + k];
    float m = fmaxf(sqrtf(ss), 1e-12f);
    sh[k] = ss / (m * m);
    __syncthreads();
    for (int o = 32; o > 0; o >>= 1) {
        if (k < o) sh[k] += sh[k + o];
        __syncthreads();
    }
    float scale2 = 1.f / fmaxf(sqrtf(sh[0]), 1e-12f);
    g_mult[b * K_ + k] = scale2 / m;
}

__global__ __launch_bounds__(256) void k_out(const float* __restrict__ centers,
                                             float* __restrict__ out) {
    const int b = blockIdx.y, d0 = blockIdx.x * 32;
    const int tid = threadIdx.x;
    const int k = tid & 63, dg = tid >> 6;
    const float ssumk = g_ssum[b * K_ + k];
    const float mult  = g_mult[b * K_ + k];
    float* op = &out[(size_t)b * D_ * K_];
#pragma unroll
    for (int t = 0; t < 8; t++) {
        int d = d0 + dg + t * 4;
        float v = g_agg[(size_t)b * D_ * K_ + (size_t)d * K_ + k] - centers[d * K_ + k] * ssumk;
        op[d * K_ + k] = v * mult;
    }
}

// ---------------------------------------------------------------------------
extern "C" void kernel_launch(void* const* d_in, const int* in_sizes, int n_in,
                              void* d_out, int out_size) {
    const float* x       = (const float*)d_in[0];  // [B, D, N]
    const float* W       = (const float*)d_in[1];  // [K, D]
    const float* centers = (const float*)d_in[2];  // [D, K]
    float* out = (float*)d_out;                    // [B, D*K]

    k_init<<<(B_ * D_ * K_ + 255) / 256, 256>>>();
    dim3 gA(N_ / 128, B_);
    kA<<<gA, 256, A_SMEM>>>(x, W);
    dim3 gB(8, B_);            // 4 d-tiles x 2 n-splits
    kB<<<gB, 256>>>(x);
    dim3 gE(D_ / 32, B_);
    k_colss<<<gE, 256>>>(centers);
    k_mult<<<B_, 64>>>();
    k_out<<<gE, 256>>>(centers, out);
}

// round 5
// speedup vs baseline: 2.6404x; 1.1157x over previous
#include <cuda_runtime.h>
#include <cuda_bf16.h>
#include <math.h>
#include <stdint.h>

#define B_ 32
#define D_ 512
#define N_ 2048
#define K_ 64

// ---------------------------------------------------------------------------
// Scratch (static device globals; no allocations allowed)
// g_scores: packed (hi,lo) bf16 per element: word = hi | (lo<<16), layout [b][k][n]
__device__ __align__(16) unsigned g_scores[(size_t)B_ * K_ * N_];   // 16 MB
__device__ __align__(16) float g_ssum[B_ * K_];
__device__ __align__(16) float g_aggp[2][(size_t)B_ * D_ * K_];     // 32 MB, split-K parts
__device__ __align__(16) float g_colss[B_ * K_];
__device__ __align__(16) float g_mult[B_ * K_];

// ---------------------------------------------------------------------------
__device__ __forceinline__ uint32_t smem_u32(const void* p) {
    uint32_t a;
    asm("{ .reg .u64 t; cvta.to.shared.u64 t, %1; cvt.u32.u64 %0, t; }" : "=r"(a) : "l"(p));
    return a;
}
__device__ __forceinline__ void ldsm4(uint32_t* r, uint32_t a) {
    asm volatile("ldmatrix.sync.aligned.m8n8.x4.shared.b16 {%0,%1,%2,%3}, [%4];"
                 : "=r"(r[0]), "=r"(r[1]), "=r"(r[2]), "=r"(r[3]) : "r"(a));
}
__device__ __forceinline__ void ldsm4t(uint32_t* r, uint32_t a) {
    asm volatile("ldmatrix.sync.aligned.m8n8.x4.trans.shared.b16 {%0,%1,%2,%3}, [%4];"
                 : "=r"(r[0]), "=r"(r[1]), "=r"(r[2]), "=r"(r[3]) : "r"(a));
}
__device__ __forceinline__ void mma_bf16(float* c, const uint32_t* a, const uint32_t* b) {
    asm volatile("mma.sync.aligned.m16n8k16.row.col.f32.bf16.bf16.f32 "
                 "{%0,%1,%2,%3}, {%4,%5,%6,%7}, {%8,%9}, {%0,%1,%2,%3};"
                 : "+f"(c[0]), "+f"(c[1]), "+f"(c[2]), "+f"(c[3])
                 : "r"(a[0]), "r"(a[1]), "r"(a[2]), "r"(a[3]), "r"(b[0]), "r"(b[1]));
}
// split two floats into packed bf16 hi-pair and lo-pair words
__device__ __forceinline__ void split2(float x, float y, uint32_t& hi, uint32_t& lo) {
    __nv_bfloat16 hx = __float2bfloat16(x), hy = __float2bfloat16(y);
    float rx = x - __bfloat162float(hx), ry = y - __bfloat162float(hy);
    __nv_bfloat16 lx = __float2bfloat16(rx), ly = __float2bfloat16(ry);
    hi = (uint32_t)__bfloat16_as_ushort(hx) | ((uint32_t)__bfloat16_as_ushort(hy) << 16);
    lo = (uint32_t)__bfloat16_as_ushort(lx) | ((uint32_t)__bfloat16_as_ushort(ly) << 16);
}

// ---------------------------------------------------------------------------
__global__ void k_init() {
    int t = blockIdx.x * blockDim.x + threadIdx.x;
    if (t < B_ * K_) { g_ssum[t] = 0.f; g_colss[t] = 0.f; }
}

// ---------------------------------------------------------------------------
// Kernel A: logits[64 k][128 n] = W @ x_tile (reduce D=512), hi/lo 3-pass MMA,
// register double-buffered, fused softmax over k, coalesced packed score writes.
// smem map (dynamic):
//   Wh @0 (5120) | Wl @5120 | Xh @10240 (8704) | Xl @18944       (loop region)
//   st  @0: f32[64][132] (33792, reused post-loop)
//   ssred @33792 (256) | st2 @34048: u32[64][128] (32768)
#define PA 40
#define PX 136
#define A_ST2  34048
#define A_SMEM (34048 + 32768)

__global__ __launch_bounds__(256) void kA(const float* __restrict__ x,
                                          const float* __restrict__ W) {
    extern __shared__ char sm[];
    const int b = blockIdx.y, n0 = blockIdx.x * 128;
    const int tid = threadIdx.x, lane = tid & 31, wid = tid >> 5;
    const int wm = wid & 3, wn = wid >> 2;

    __nv_bfloat16* Wh = (__nv_bfloat16*)(sm);
    __nv_bfloat16* Wl = (__nv_bfloat16*)(sm + 5120);
    __nv_bfloat16* Xh = (__nv_bfloat16*)(sm + 10240);
    __nv_bfloat16* Xl = (__nv_bfloat16*)(sm + 18944);
    const uint32_t wh_a = smem_u32(Wh), wl_a = smem_u32(Wl);
    const uint32_t xh_a = smem_u32(Xh), xl_a = smem_u32(Xl);

    // load indices
    const int wk = tid >> 3, wdd = (tid & 7) * 4;        // W: k row, d offset
    const int xnn = lane * 4;                            // x: n offset

    float acc[8][4];
#pragma unroll
    for (int i = 0; i < 8; i++)
#pragma unroll
        for (int j = 0; j < 4; j++) acc[i][j] = 0.f;

    float4 wbuf[2], xbuf[4];
    // prefetch chunk 0
#pragma unroll
    for (int p = 0; p < 2; p++)
        wbuf[p] = *(const float4*)&W[(wk + p * 32) * D_ + wdd];
#pragma unroll
    for (int p = 0; p < 4; p++)
        xbuf[p] = *(const float4*)&x[((size_t)b * D_ + wid + p * 8) * N_ + n0 + xnn];

    for (int c = 0; c < 16; c++) {
        // store current chunk regs -> smem (with hi/lo split)
#pragma unroll
        for (int p = 0; p < 2; p++) {
            int k = wk + p * 32;
            uint32_t h0, l0, h1, l1;
            split2(wbuf[p].x, wbuf[p].y, h0, l0);
            split2(wbuf[p].z, wbuf[p].w, h1, l1);
            int off = k * PA + wdd;
            *(uint32_t*)&Wh[off] = h0; *(uint32_t*)&Wh[off + 2] = h1;
            *(uint32_t*)&Wl[off] = l0; *(uint32_t*)&Wl[off + 2] = l1;
        }
#pragma unroll
        for (int p = 0; p < 4; p++) {
            int dd = wid + p * 8;
            uint32_t h0, l0, h1, l1;
            split2(xbuf[p].x, xbuf[p].y, h0, l0);
            split2(xbuf[p].z, xbuf[p].w, h1, l1);
            int off = dd * PX + xnn;
            *(uint32_t*)&Xh[off] = h0; *(uint32_t*)&Xh[off + 2] = h1;
            *(uint32_t*)&Xl[off] = l0; *(uint32_t*)&Xl[off + 2] = l1;
        }
        __syncthreads();

        // prefetch next chunk (latency overlapped with MMA below)
        if (c < 15) {
            int d1 = (c + 1) * 32;
#pragma unroll
            for (int p = 0; p < 2; p++)
                wbuf[p] = *(const float4*)&W[(wk + p * 32) * D_ + d1 + wdd];
#pragma unroll
            for (int p = 0; p < 4; p++)
                xbuf[p] = *(const float4*)&x[((size_t)b * D_ + d1 + wid + p * 8) * N_ + n0 + xnn];
        }

#pragma unroll
        for (int ks = 0; ks < 2; ks++) {
            uint32_t ah[4], al[4];
            uint32_t aoff = (uint32_t)(((wm * 16 + (lane & 15)) * PA + ks * 16 + (lane >> 4) * 8) * 2);
            ldsm4(ah, wh_a + aoff);
            ldsm4(al, wl_a + aoff);
#pragma unroll
            for (int nf = 0; nf < 4; nf++) {
                uint32_t bh[4], bl[4];
                uint32_t boff = (uint32_t)(((ks * 16 + (lane & 15)) * PX +
                                            wn * 64 + nf * 16 + (lane >> 4) * 8) * 2);
                ldsm4t(bh, xh_a + boff);
                ldsm4t(bl, xl_a + boff);
                mma_bf16(acc[nf * 2],     ah, bh);
                mma_bf16(acc[nf * 2],     ah, bl);
                mma_bf16(acc[nf * 2],     al, bh);
                mma_bf16(acc[nf * 2 + 1], ah, bh + 2);
                mma_bf16(acc[nf * 2 + 1], ah, bl + 2);
                mma_bf16(acc[nf * 2 + 1], al, bh + 2);
            }
        }
        __syncthreads();
    }

    // stash logits tile to smem [64][132] f32
    float* st = (float*)sm;
    {
        int g = lane >> 2, tg = lane & 3;
        int r0 = wm * 16 + g;
#pragma unroll
        for (int nf = 0; nf < 8; nf++) {
            int cix = wn * 64 + nf * 8 + tg * 2;
            st[r0 * 132 + cix]           = acc[nf][0];
            st[r0 * 132 + cix + 1]       = acc[nf][1];
            st[(r0 + 8) * 132 + cix]     = acc[nf][2];
            st[(r0 + 8) * 132 + cix + 1] = acc[nf][3];
        }
    }
    float* ssred = (float*)(sm + 33792);
    unsigned* st2 = (unsigned*)(sm + A_ST2);
    if (tid < 64) ssred[tid] = 0.f;
    __syncthreads();

    // softmax over k per column (threads 0..127), results into st2 (smem)
    if (tid < 128) {
        int col = tid;
        float m = -1e30f;
#pragma unroll
        for (int k = 0; k < 64; k++) m = fmaxf(m, st[k * 132 + col]);
        float s = 0.f;
#pragma unroll
        for (int k = 0; k < 64; k++) s += __expf(st[k * 132 + col] - m);
        float inv = 1.f / s;
#pragma unroll
        for (int k = 0; k < 64; k++) {
            float v = __expf(st[k * 132 + col] - m) * inv;
            __nv_bfloat16 h = __float2bfloat16(v);
            float r = v - __bfloat162float(h);
            __nv_bfloat16 l = __float2bfloat16(r);
            st2[k * 128 + col] = (uint32_t)__bfloat16_as_ushort(h) |
                                 ((uint32_t)__bfloat16_as_ushort(l) << 16);
            float ws = v;
#pragma unroll
            for (int o = 16; o > 0; o >>= 1) ws += __shfl_xor_sync(0xffffffff, ws, o);
            if (lane == 0) atomicAdd(&ssred[k], ws);
        }
    }
    __syncthreads();

    // coalesced packed score writes: warp w owns rows w*8..w*8+7, uint4 per thread
#pragma unroll
    for (int r = 0; r < 8; r++) {
        int row = wid * 8 + r;
        uint4 v = ((const uint4*)&st2[row * 128])[lane];
        ((uint4*)&g_scores[((size_t)b * K_ + row) * N_ + n0])[lane] = v;
    }
    if (tid < 64) atomicAdd(&g_ssum[b * K_ + tid], ssred[tid]);
}

// ---------------------------------------------------------------------------
// Kernel B: agg_part[sp][128 d][64 k] = x_tile @ scores^T (reduce n over 1024),
// register double-buffered, non-atomic split-K output.
#define PB 40
__global__ __launch_bounds__(256) void kB(const float* __restrict__ x) {
    __shared__ __align__(16) __nv_bfloat16 Xh[128 * PB];
    __shared__ __align__(16) __nv_bfloat16 Xl[128 * PB];
    __shared__ __align__(16) __nv_bfloat16 Sh[64 * PB];
    __shared__ __align__(16) __nv_bfloat16 Sl[64 * PB];
    const int b = blockIdx.y;
    const int d0 = (blockIdx.x & 3) * 128;
    const int sp = blockIdx.x >> 2;
    const int spn = sp * 1024;
    const int tid = threadIdx.x, lane = tid & 31, wid = tid >> 5;
    const uint32_t xh_a = smem_u32(Xh), xl_a = smem_u32(Xl);
    const uint32_t sh_a = smem_u32(Sh), sl_a = smem_u32(Sl);

    const int xrr = tid >> 3, xnn = (tid & 7) * 4;     // x: d row base, n offset
    const int sk = tid >> 4, sn2 = (tid & 15) * 2;     // scores: k row base, n offset

    float acc[8][4];
#pragma unroll
    for (int i = 0; i < 8; i++)
#pragma unroll
        for (int j = 0; j < 4; j++) acc[i][j] = 0.f;

    float4 xbuf[4];
    uint2  sbuf[4];
#pragma unroll
    for (int p = 0; p < 4; p++)
        xbuf[p] = *(const float4*)&x[((size_t)b * D_ + d0 + xrr + p * 32) * N_ + spn + xnn];
#pragma unroll
    for (int p = 0; p < 4; p++)
        sbuf[p] = *(const uint2*)&g_scores[((size_t)b * K_ + sk + p * 16) * N_ + spn + sn2];

    for (int c = 0; c < 32; c++) {
        // store current chunk -> smem
#pragma unroll
        for (int p = 0; p < 4; p++) {
            int rr = xrr + p * 32;
            uint32_t h0, l0, h1, l1;
            split2(xbuf[p].x, xbuf[p].y, h0, l0);
            split2(xbuf[p].z, xbuf[p].w, h1, l1);
            int off = rr * PB + xnn;
            *(uint32_t*)&Xh[off] = h0; *(uint32_t*)&Xh[off + 2] = h1;
            *(uint32_t*)&Xl[off] = l0; *(uint32_t*)&Xl[off + 2] = l1;
        }
#pragma unroll
        for (int p = 0; p < 4; p++) {
            int k = sk + p * 16;
            int off = k * PB + sn2;
            *(uint32_t*)&Sh[off] = __byte_perm(sbuf[p].x, sbuf[p].y, 0x5410);
            *(uint32_t*)&Sl[off] = __byte_perm(sbuf[p].x, sbuf[p].y, 0x7632);
        }
        __syncthreads();

        // prefetch next chunk
        if (c < 31) {
            int n1 = spn + (c + 1) * 32;
#pragma unroll
            for (int p = 0; p < 4; p++)
                xbuf[p] = *(const float4*)&x[((size_t)b * D_ + d0 + xrr + p * 32) * N_ + n1 + xnn];
#pragma unroll
            for (int p = 0; p < 4; p++)
                sbuf[p] = *(const uint2*)&g_scores[((size_t)b * K_ + sk + p * 16) * N_ + n1 + sn2];
        }

#pragma unroll
        for (int ks = 0; ks < 2; ks++) {
            uint32_t ah[4], al[4];
            uint32_t aoff = (uint32_t)(((wid * 16 + (lane & 15)) * PB + ks * 16 + (lane >> 4) * 8) * 2);
            ldsm4(ah, xh_a + aoff);
            ldsm4(al, xl_a + aoff);
#pragma unroll
            for (int nf = 0; nf < 4; nf++) {
                uint32_t bh[4], bl[4];
                uint32_t boff = (uint32_t)(((nf * 16 + (lane & 7) + ((lane >> 4) << 3)) * PB +
                                            ks * 16 + ((lane >> 3) & 1) * 8) * 2);
                ldsm4(bh, sh_a + boff);
                ldsm4(bl, sl_a + boff);
                mma_bf16(acc[nf * 2],     ah, bh);
                mma_bf16(acc[nf * 2],     ah, bl);
                mma_bf16(acc[nf * 2],     al, bh);
                mma_bf16(acc[nf * 2 + 1], ah, bh + 2);
                mma_bf16(acc[nf * 2 + 1], ah, bl + 2);
                mma_bf16(acc[nf * 2 + 1], al, bh + 2);
            }
        }
        __syncthreads();
    }

    // non-atomic writes into this split's partial buffer
    int g = lane >> 2, tg = lane & 3;
    int d = d0 + wid * 16 + g;
    float* base = &g_aggp[sp][((size_t)b * D_ + d) * K_];
#pragma unroll
    for (int nf = 0; nf < 8; nf++) {
        int cix = nf * 8 + tg * 2;
        base[cix]              = acc[nf][0];
        base[cix + 1]          = acc[nf][1];
        base[8 * K_ + cix]     = acc[nf][2];
        base[8 * K_ + cix + 1] = acc[nf][3];
    }
}

// ---------------------------------------------------------------------------
// Epilogue
__global__ __launch_bounds__(256) void k_colss(const float* __restrict__ centers) {
    const int b = blockIdx.y, d0 = blockIdx.x * 32;
    const int tid = threadIdx.x;
    const int k = tid & 63, dg = tid >> 6;
    __shared__ float red[4][64];
    const float ssumk = g_ssum[b * K_ + k];
    float acc = 0.f;
#pragma unroll
    for (int t = 0; t < 8; t++) {
        int d = d0 + dg + t * 4;
        size_t idx = (size_t)b * D_ * K_ + (size_t)d * K_ + k;
        float v = g_aggp[0][idx] + g_aggp[1][idx] - centers[d * K_ + k] * ssumk;
        acc = fmaf(v, v, acc);
    }
    red[dg][k] = acc;
    __syncthreads();
    if (tid < 64) {
        float tot = red[0][tid] + red[1][tid] + red[2][tid] + red[3][tid];
        atomicAdd(&g_colss[b * K_ + tid], tot);
    }
}

__global__ void k_mult() {
    const int b = blockIdx.x, k = threadIdx.x;
    __shared__ float sh[64];
    float ss = g_colss[b * K_ + k];
    float m = fmaxf(sqrtf(ss), 1e-12f);
    sh[k] = ss / (m * m);
    __syncthreads();
    for (int o = 32; o > 0; o >>= 1) {
        if (k < o) sh[k] += sh[k + o];
        __syncthreads();
    }
    float scale2 = 1.f / fmaxf(sqrtf(sh[0]), 1e-12f);
    g_mult[b * K_ + k] = scale2 / m;
}

__global__ __launch_bounds__(256) void k_out(const float* __restrict__ centers,
                                             float* __restrict__ out) {
    const int b = blockIdx.y, d0 = blockIdx.x * 32;
    const int tid = threadIdx.x;
    const int k = tid & 63, dg = tid >> 6;
    const float ssumk = g_ssum[b * K_ + k];
    const float mult  = g_mult[b * K_ + k];
    float* op = &out[(size_t)b * D_ * K_];
#pragma unroll
    for (int t = 0; t < 8; t++) {
        int d = d0 + dg + t * 4;
        size_t idx = (size_t)b * D_ * K_ + (size_t)d * K_ + k;
        float v = g_aggp[0][idx] + g_aggp[1][idx] - centers[d * K_ + k] * ssumk;
        op[d * K_ + k] = v * mult;
    }
}

// ---------------------------------------------------------------------------
extern "C" void kernel_launch(void* const* d_in, const int* in_sizes, int n_in,
                              void* d_out, int out_size) {
    const float* x       = (const float*)d_in[0];  // [B, D, N]
    const float* W       = (const float*)d_in[1];  // [K, D]
    const float* centers = (const float*)d_in[2];  // [D, K]
    float* out = (float*)d_out;                    // [B, D*K]

    cudaFuncSetAttribute(kA, cudaFuncAttributeMaxDynamicSharedMemorySize, A_SMEM);

    k_init<<<8, 256>>>();
    dim3 gA(N_ / 128, B_);
    kA<<<gA, 256, A_SMEM>>>(x, W);
    dim3 gB(8, B_);            // 4 d-tiles x 2 n-splits
    kB<<<gB, 256>>>(x);
    dim3 gE(D_ / 32, B_);
    k_colss<<<gE, 256>>>(centers);
    k_mult<<<B_, 64>>>();
    k_out<<<gE, 256>>>(centers, out);
}

// round 6
// speedup vs baseline: 2.8244x; 1.0697x over previous
#include <cuda_runtime.h>
#include <cuda_bf16.h>
#include <math.h>
#include <stdint.h>

#define B_ 32
#define D_ 512
#define N_ 2048
#define K_ 64

// ---------------------------------------------------------------------------
// Scratch (static device globals; no allocations allowed)
// g_scores: packed (hi,lo) bf16 per element: word = hi | (lo<<16), layout [b][k][n]
__device__ __align__(16) unsigned g_scores[(size_t)B_ * K_ * N_];   // 16 MB
__device__ __align__(16) float g_ssum[B_ * K_];
__device__ __align__(16) float g_aggp[4][(size_t)B_ * D_ * K_];     // 4 split-K parts
__device__ __align__(16) float g_colss[B_ * K_];
__device__ __align__(16) float g_mult[B_ * K_];

// ---------------------------------------------------------------------------
__device__ __forceinline__ uint32_t smem_u32(const void* p) {
    uint32_t a;
    asm("{ .reg .u64 t; cvta.to.shared.u64 t, %1; cvt.u32.u64 %0, t; }" : "=r"(a) : "l"(p));
    return a;
}
__device__ __forceinline__ void ldsm4(uint32_t* r, uint32_t a) {
    asm volatile("ldmatrix.sync.aligned.m8n8.x4.shared.b16 {%0,%1,%2,%3}, [%4];"
                 : "=r"(r[0]), "=r"(r[1]), "=r"(r[2]), "=r"(r[3]) : "r"(a));
}
__device__ __forceinline__ void ldsm4t(uint32_t* r, uint32_t a) {
    asm volatile("ldmatrix.sync.aligned.m8n8.x4.trans.shared.b16 {%0,%1,%2,%3}, [%4];"
                 : "=r"(r[0]), "=r"(r[1]), "=r"(r[2]), "=r"(r[3]) : "r"(a));
}
__device__ __forceinline__ void mma_bf16(float* c, const uint32_t* a, const uint32_t* b) {
    asm volatile("mma.sync.aligned.m16n8k16.row.col.f32.bf16.bf16.f32 "
                 "{%0,%1,%2,%3}, {%4,%5,%6,%7}, {%8,%9}, {%0,%1,%2,%3};"
                 : "+f"(c[0]), "+f"(c[1]), "+f"(c[2]), "+f"(c[3])
                 : "r"(a[0]), "r"(a[1]), "r"(a[2]), "r"(a[3]), "r"(b[0]), "r"(b[1]));
}
__device__ __forceinline__ void split2(float x, float y, uint32_t& hi, uint32_t& lo) {
    __nv_bfloat16 hx = __float2bfloat16(x), hy = __float2bfloat16(y);
    float rx = x - __bfloat162float(hx), ry = y - __bfloat162float(hy);
    __nv_bfloat16 lx = __float2bfloat16(rx), ly = __float2bfloat16(ry);
    hi = (uint32_t)__bfloat16_as_ushort(hx) | ((uint32_t)__bfloat16_as_ushort(hy) << 16);
    lo = (uint32_t)__bfloat16_as_ushort(lx) | ((uint32_t)__bfloat16_as_ushort(ly) << 16);
}

// ---------------------------------------------------------------------------
__global__ void k_init() {
    int t = blockIdx.x * blockDim.x + threadIdx.x;
    if (t < B_ * K_) { g_ssum[t] = 0.f; g_colss[t] = 0.f; }
}

// ---------------------------------------------------------------------------
// Kernel A: logits[64 k][128 n] = W @ x_tile (reduce D=512), hi/lo 3-pass MMA,
// smem double-buffered (1 sync/chunk), register prefetch, fused softmax,
// coalesced packed score writes.
// smem: buf0 @0, buf1 @27648 (each: Wh 5120 | Wl 5120 | Xh 8704 | Xl 8704)
// post-loop reuse: st f32[64][132] @0 | ssred @33792 | st2 u32[64][128] @34048
#define PA 40
#define PX 136
#define A_BUF  27648
#define A_ST2  34048
#define A_SMEM (34048 + 32768)

__global__ __launch_bounds__(256) void kA(const float* __restrict__ x,
                                          const float* __restrict__ W) {
    extern __shared__ char sm[];
    const int b = blockIdx.y, n0 = blockIdx.x * 128;
    const int tid = threadIdx.x, lane = tid & 31, wid = tid >> 5;
    const int wm = wid & 3, wn = wid >> 2;
    const uint32_t smb = smem_u32(sm);

    const int wk = tid >> 3, wdd = (tid & 7) * 4;        // W: k row, d offset
    const int xnn = lane * 4;                            // x: n offset

    float acc[8][4];
#pragma unroll
    for (int i = 0; i < 8; i++)
#pragma unroll
        for (int j = 0; j < 4; j++) acc[i][j] = 0.f;

    float4 wbuf[2], xbuf[4];
#pragma unroll
    for (int p = 0; p < 2; p++)
        wbuf[p] = *(const float4*)&W[(wk + p * 32) * D_ + wdd];
#pragma unroll
    for (int p = 0; p < 4; p++)
        xbuf[p] = *(const float4*)&x[((size_t)b * D_ + wid + p * 8) * N_ + n0 + xnn];

    for (int c = 0; c < 16; c++) {
        char* bufc = sm + (c & 1) * A_BUF;
        __nv_bfloat16* Wh = (__nv_bfloat16*)(bufc);
        __nv_bfloat16* Wl = (__nv_bfloat16*)(bufc + 5120);
        __nv_bfloat16* Xh = (__nv_bfloat16*)(bufc + 10240);
        __nv_bfloat16* Xl = (__nv_bfloat16*)(bufc + 18944);

        // store current chunk regs -> smem (hi/lo split)
#pragma unroll
        for (int p = 0; p < 2; p++) {
            int k = wk + p * 32;
            uint32_t h0, l0, h1, l1;
            split2(wbuf[p].x, wbuf[p].y, h0, l0);
            split2(wbuf[p].z, wbuf[p].w, h1, l1);
            int off = k * PA + wdd;
            *(uint32_t*)&Wh[off] = h0; *(uint32_t*)&Wh[off + 2] = h1;
            *(uint32_t*)&Wl[off] = l0; *(uint32_t*)&Wl[off + 2] = l1;
        }
#pragma unroll
        for (int p = 0; p < 4; p++) {
            int dd = wid + p * 8;
            uint32_t h0, l0, h1, l1;
            split2(xbuf[p].x, xbuf[p].y, h0, l0);
            split2(xbuf[p].z, xbuf[p].w, h1, l1);
            int off = dd * PX + xnn;
            *(uint32_t*)&Xh[off] = h0; *(uint32_t*)&Xh[off + 2] = h1;
            *(uint32_t*)&Xl[off] = l0; *(uint32_t*)&Xl[off + 2] = l1;
        }
        __syncthreads();

        // prefetch next chunk (overlapped with MMA below)
        if (c < 15) {
            int d1 = (c + 1) * 32;
#pragma unroll
            for (int p = 0; p < 2; p++)
                wbuf[p] = *(const float4*)&W[(wk + p * 32) * D_ + d1 + wdd];
#pragma unroll
            for (int p = 0; p < 4; p++)
                xbuf[p] = *(const float4*)&x[((size_t)b * D_ + d1 + wid + p * 8) * N_ + n0 + xnn];
        }

        const uint32_t wh_a = smb + (c & 1) * A_BUF;
        const uint32_t wl_a = wh_a + 5120;
        const uint32_t xh_a = wh_a + 10240;
        const uint32_t xl_a = wh_a + 18944;
#pragma unroll
        for (int ks = 0; ks < 2; ks++) {
            uint32_t ah[4], al[4];
            uint32_t aoff = (uint32_t)(((wm * 16 + (lane & 15)) * PA + ks * 16 + (lane >> 4) * 8) * 2);
            ldsm4(ah, wh_a + aoff);
            ldsm4(al, wl_a + aoff);
#pragma unroll
            for (int nf = 0; nf < 4; nf++) {
                uint32_t bh[4], bl[4];
                uint32_t boff = (uint32_t)(((ks * 16 + (lane & 15)) * PX +
                                            wn * 64 + nf * 16 + (lane >> 4) * 8) * 2);
                ldsm4t(bh, xh_a + boff);
                ldsm4t(bl, xl_a + boff);
                mma_bf16(acc[nf * 2],     ah, bh);
                mma_bf16(acc[nf * 2],     ah, bl);
                mma_bf16(acc[nf * 2],     al, bh);
                mma_bf16(acc[nf * 2 + 1], ah, bh + 2);
                mma_bf16(acc[nf * 2 + 1], ah, bl + 2);
                mma_bf16(acc[nf * 2 + 1], al, bh + 2);
            }
        }
        // no second sync: iter c+1 stores hit buf[(c+1)&1], last read at iter c-1
    }
    __syncthreads();

    // stash logits tile to smem [64][132] f32
    float* st = (float*)sm;
    {
        int g = lane >> 2, tg = lane & 3;
        int r0 = wm * 16 + g;
#pragma unroll
        for (int nf = 0; nf < 8; nf++) {
            int cix = wn * 64 + nf * 8 + tg * 2;
            st[r0 * 132 + cix]           = acc[nf][0];
            st[r0 * 132 + cix + 1]       = acc[nf][1];
            st[(r0 + 8) * 132 + cix]     = acc[nf][2];
            st[(r0 + 8) * 132 + cix + 1] = acc[nf][3];
        }
    }
    float* ssred = (float*)(sm + 33792);
    unsigned* st2 = (unsigned*)(sm + A_ST2);
    if (tid < 64) ssred[tid] = 0.f;
    __syncthreads();

    // softmax over k per column (threads 0..127); cache exp in st
    if (tid < 128) {
        int col = tid;
        float m = -1e30f;
#pragma unroll
        for (int k = 0; k < 64; k++) m = fmaxf(m, st[k * 132 + col]);
        float s = 0.f;
#pragma unroll
        for (int k = 0; k < 64; k++) {
            float e = __expf(st[k * 132 + col] - m);
            st[k * 132 + col] = e;
            s += e;
        }
        float inv = 1.f / s;
#pragma unroll
        for (int k = 0; k < 64; k++) {
            float v = st[k * 132 + col] * inv;
            __nv_bfloat16 h = __float2bfloat16(v);
            float r = v - __bfloat162float(h);
            __nv_bfloat16 l = __float2bfloat16(r);
            st2[k * 128 + col] = (uint32_t)__bfloat16_as_ushort(h) |
                                 ((uint32_t)__bfloat16_as_ushort(l) << 16);
            float ws = v;
#pragma unroll
            for (int o = 16; o > 0; o >>= 1) ws += __shfl_xor_sync(0xffffffff, ws, o);
            if (lane == 0) atomicAdd(&ssred[k], ws);
        }
    }
    __syncthreads();

    // coalesced packed score writes
#pragma unroll
    for (int r = 0; r < 8; r++) {
        int row = wid * 8 + r;
        uint4 v = ((const uint4*)&st2[row * 128])[lane];
        ((uint4*)&g_scores[((size_t)b * K_ + row) * N_ + n0])[lane] = v;
    }
    if (tid < 64) atomicAdd(&g_ssum[b * K_ + tid], ssred[tid]);
}

// ---------------------------------------------------------------------------
// Kernel B: agg_part[sp][128 d][64 k] = x_tile @ scores^T (reduce 512 n),
// smem double-buffered (1 sync/chunk), register prefetch, split-K 4.
// smem per buf: Xh 10240 | Xl 10240 | Sh 5120 | Sl 5120 = 30720; x2 = 61440
#define PB 40
#define B_BUF  30720
#define B_SMEM (2 * B_BUF)

__global__ __launch_bounds__(256) void kB(const float* __restrict__ x) {
    extern __shared__ char sm[];
    const int b = blockIdx.y;
    const int d0 = (blockIdx.x & 3) * 128;
    const int sp = blockIdx.x >> 2;
    const int spn = sp * 512;
    const int tid = threadIdx.x, lane = tid & 31, wid = tid >> 5;
    const uint32_t smb = smem_u32(sm);

    const int xrr = tid >> 3, xnn = (tid & 7) * 4;     // x: d row base, n offset
    const int sk = tid >> 4, sn2 = (tid & 15) * 2;     // scores: k row base, n offset

    float acc[8][4];
#pragma unroll
    for (int i = 0; i < 8; i++)
#pragma unroll
        for (int j = 0; j < 4; j++) acc[i][j] = 0.f;

    float4 xbuf[4];
    uint2  sbuf[4];
#pragma unroll
    for (int p = 0; p < 4; p++)
        xbuf[p] = *(const float4*)&x[((size_t)b * D_ + d0 + xrr + p * 32) * N_ + spn + xnn];
#pragma unroll
    for (int p = 0; p < 4; p++)
        sbuf[p] = *(const uint2*)&g_scores[((size_t)b * K_ + sk + p * 16) * N_ + spn + sn2];

    for (int c = 0; c < 16; c++) {
        char* bufc = sm + (c & 1) * B_BUF;
        __nv_bfloat16* Xh = (__nv_bfloat16*)(bufc);
        __nv_bfloat16* Xl = (__nv_bfloat16*)(bufc + 10240);
        __nv_bfloat16* Sh = (__nv_bfloat16*)(bufc + 20480);
        __nv_bfloat16* Sl = (__nv_bfloat16*)(bufc + 25600);

#pragma unroll
        for (int p = 0; p < 4; p++) {
            int rr = xrr + p * 32;
            uint32_t h0, l0, h1, l1;
            split2(xbuf[p].x, xbuf[p].y, h0, l0);
            split2(xbuf[p].z, xbuf[p].w, h1, l1);
            int off = rr * PB + xnn;
            *(uint32_t*)&Xh[off] = h0; *(uint32_t*)&Xh[off + 2] = h1;
            *(uint32_t*)&Xl[off] = l0; *(uint32_t*)&Xl[off + 2] = l1;
        }
#pragma unroll
        for (int p = 0; p < 4; p++) {
            int k = sk + p * 16;
            int off = k * PB + sn2;
            *(uint32_t*)&Sh[off] = __byte_perm(sbuf[p].x, sbuf[p].y, 0x5410);
            *(uint32_t*)&Sl[off] = __byte_perm(sbuf[p].x, sbuf[p].y, 0x7632);
        }
        __syncthreads();

        if (c < 15) {
            int n1 = spn + (c + 1) * 32;
#pragma unroll
            for (int p = 0; p < 4; p++)
                xbuf[p] = *(const float4*)&x[((size_t)b * D_ + d0 + xrr + p * 32) * N_ + n1 + xnn];
#pragma unroll
            for (int p = 0; p < 4; p++)
                sbuf[p] = *(const uint2*)&g_scores[((size_t)b * K_ + sk + p * 16) * N_ + n1 + sn2];
        }

        const uint32_t xh_a = smb + (c & 1) * B_BUF;
        const uint32_t xl_a = xh_a + 10240;
        const uint32_t sh_a = xh_a + 20480;
        const uint32_t sl_a = xh_a + 25600;
#pragma unroll
        for (int ks = 0; ks < 2; ks++) {
            uint32_t ah[4], al[4];
            uint32_t aoff = (uint32_t)(((wid * 16 + (lane & 15)) * PB + ks * 16 + (lane >> 4) * 8) * 2);
            ldsm4(ah, xh_a + aoff);
            ldsm4(al, xl_a + aoff);
#pragma unroll
            for (int nf = 0; nf < 4; nf++) {
                uint32_t bh[4], bl[4];
                uint32_t boff = (uint32_t)(((nf * 16 + (lane & 7) + ((lane >> 4) << 3)) * PB +
                                            ks * 16 + ((lane >> 3) & 1) * 8) * 2);
                ldsm4(bh, sh_a + boff);
                ldsm4(bl, sl_a + boff);
                mma_bf16(acc[nf * 2],     ah, bh);
                mma_bf16(acc[nf * 2],     ah, bl);
                mma_bf16(acc[nf * 2],     al, bh);
                mma_bf16(acc[nf * 2 + 1], ah, bh + 2);
                mma_bf16(acc[nf * 2 + 1], ah, bl + 2);
                mma_bf16(acc[nf * 2 + 1], al, bh + 2);
            }
        }
    }

    // non-atomic writes into this split's partial buffer
    int g = lane >> 2, tg = lane & 3;
    int d = d0 + wid * 16 + g;
    float* base = &g_aggp[sp][((size_t)b * D_ + d) * K_];
#pragma unroll
    for (int nf = 0; nf < 8; nf++) {
        int cix = nf * 8 + tg * 2;
        base[cix]              = acc[nf][0];
        base[cix + 1]          = acc[nf][1];
        base[8 * K_ + cix]     = acc[nf][2];
        base[8 * K_ + cix + 1] = acc[nf][3];
    }
}

// ---------------------------------------------------------------------------
// Epilogue: k_colss sums 4 parts, applies center bias, writes v back to part 0,
// accumulates per-(b,k) sumsq.
__global__ __launch_bounds__(256) void k_colss(const float* __restrict__ centers) {
    const int b = blockIdx.y, d0 = blockIdx.x * 32;
    const int tid = threadIdx.x;
    const int k = tid & 63, dg = tid >> 6;
    __shared__ float red[4][64];
    const float ssumk = g_ssum[b * K_ + k];
    float acc = 0.f;
#pragma unroll
    for (int t = 0; t < 8; t++) {
        int d = d0 + dg + t * 4;
        size_t idx = (size_t)b * D_ * K_ + (size_t)d * K_ + k;
        float v = g_aggp[0][idx] + g_aggp[1][idx] + g_aggp[2][idx] + g_aggp[3][idx]
                  - centers[d * K_ + k] * ssumk;
        g_aggp[0][idx] = v;
        acc = fmaf(v, v, acc);
    }
    red[dg][k] = acc;
    __syncthreads();
    if (tid < 64) {
        float tot = red[0][tid] + red[1][tid] + red[2][tid] + red[3][tid];
        atomicAdd(&g_colss[b * K_ + tid], tot);
    }
}

__global__ void k_mult() {
    const int b = blockIdx.x, k = threadIdx.x;
    __shared__ float sh[64];
    float ss = g_colss[b * K_ + k];
    float m = fmaxf(sqrtf(ss), 1e-12f);
    sh[k] = ss / (m * m);
    __syncthreads();
    for (int o = 32; o > 0; o >>= 1) {
        if (k < o) sh[k] += sh[k + o];
        __syncthreads();
    }
    float scale2 = 1.f / fmaxf(sqrtf(sh[0]), 1e-12f);
    g_mult[b * K_ + k] = scale2 / m;
}

__global__ __launch_bounds__(256) void k_out(float* __restrict__ out) {
    const int b = blockIdx.y, d0 = blockIdx.x * 32;
    const int tid = threadIdx.x;
    const int k = tid & 63, dg = tid >> 6;
    const float mult = g_mult[b * K_ + k];
    float* op = &out[(size_t)b * D_ * K_];
#pragma unroll
    for (int t = 0; t < 8; t++) {
        int d = d0 + dg + t * 4;
        size_t idx = (size_t)b * D_ * K_ + (size_t)d * K_ + k;
        op[d * K_ + k] = g_aggp[0][idx] * mult;
    }
}

// ---------------------------------------------------------------------------
extern "C" void kernel_launch(void* const* d_in, const int* in_sizes, int n_in,
                              void* d_out, int out_size) {
    const float* x       = (const float*)d_in[0];  // [B, D, N]
    const float* W       = (const float*)d_in[1];  // [K, D]
    const float* centers = (const float*)d_in[2];  // [D, K]
    float* out = (float*)d_out;                    // [B, D*K]

    cudaFuncSetAttribute(kA, cudaFuncAttributeMaxDynamicSharedMemorySize, A_SMEM);
    cudaFuncSetAttribute(kB, cudaFuncAttributeMaxDynamicSharedMemorySize, B_SMEM);

    k_init<<<8, 256>>>();
    dim3 gA(N_ / 128, B_);
    kA<<<gA, 256, A_SMEM>>>(x, W);
    dim3 gB(16, B_);           // 4 d-tiles x 4 n-splits
    kB<<<gB, 256, B_SMEM>>>(x);
    dim3 gE(D_ / 32, B_);
    k_colss<<<gE, 256>>>(centers);
    k_mult<<<B_, 64>>>();
    k_out<<<gE, 256>>>(out);
}

// round 7
// speedup vs baseline: 2.9954x; 1.0606x over previous
#include <cuda_runtime.h>
#include <cuda_bf16.h>
#include <math.h>
#include <stdint.h>

#define B_ 32
#define D_ 512
#define N_ 2048
#define K_ 64

// ---------------------------------------------------------------------------
// Scratch (static device globals; no allocations allowed)
__device__ __align__(16) __nv_bfloat16 g_Wh[K_ * D_];               // W hi plane
__device__ __align__(16) __nv_bfloat16 g_Wl[K_ * D_];               // W lo plane
__device__ __align__(16) __nv_bfloat16 g_Sh[(size_t)B_ * K_ * N_];  // scores hi
__device__ __align__(16) __nv_bfloat16 g_Sl[(size_t)B_ * K_ * N_];  // scores lo
__device__ __align__(16) float g_ssum[B_ * K_];
__device__ __align__(16) float g_aggp[4][(size_t)B_ * D_ * K_];     // split-K parts
__device__ __align__(16) float g_colss[B_ * K_];
__device__ __align__(16) float g_mult[B_ * K_];

// ---------------------------------------------------------------------------
__device__ __forceinline__ uint32_t smem_u32(const void* p) {
    uint32_t a;
    asm("{ .reg .u64 t; cvta.to.shared.u64 t, %1; cvt.u32.u64 %0, t; }" : "=r"(a) : "l"(p));
    return a;
}
__device__ __forceinline__ void ldsm4(uint32_t* r, uint32_t a) {
    asm volatile("ldmatrix.sync.aligned.m8n8.x4.shared.b16 {%0,%1,%2,%3}, [%4];"
                 : "=r"(r[0]), "=r"(r[1]), "=r"(r[2]), "=r"(r[3]) : "r"(a));
}
__device__ __forceinline__ void ldsm4t(uint32_t* r, uint32_t a) {
    asm volatile("ldmatrix.sync.aligned.m8n8.x4.trans.shared.b16 {%0,%1,%2,%3}, [%4];"
                 : "=r"(r[0]), "=r"(r[1]), "=r"(r[2]), "=r"(r[3]) : "r"(a));
}
__device__ __forceinline__ void mma_bf16(float* c, const uint32_t* a, const uint32_t* b) {
    asm volatile("mma.sync.aligned.m16n8k16.row.col.f32.bf16.bf16.f32 "
                 "{%0,%1,%2,%3}, {%4,%5,%6,%7}, {%8,%9}, {%0,%1,%2,%3};"
                 : "+f"(c[0]), "+f"(c[1]), "+f"(c[2]), "+f"(c[3])
                 : "r"(a[0]), "r"(a[1]), "r"(a[2]), "r"(a[3]), "r"(b[0]), "r"(b[1]));
}
// packed bf16x2 convert: returns lo | hi<<16
__device__ __forceinline__ uint32_t cvt2(float lo, float hi) {
    uint32_t r;
    asm("cvt.rn.satfinite.bf16x2.f32 %0, %1, %2;" : "=r"(r) : "f"(hi), "f"(lo));
    return r;
}
// hi/lo split of two floats, 6 instrs
__device__ __forceinline__ void split2(float x, float y, uint32_t& hi, uint32_t& lo) {
    hi = cvt2(x, y);
    float hx = __uint_as_float(hi << 16);
    float hy = __uint_as_float(hi & 0xffff0000u);
    lo = cvt2(x - hx, y - hy);
}
// cp.async 16B
#define CP16(dst, src) asm volatile("cp.async.cg.shared.global [%0], [%1], 16;" :: "r"(dst), "l"(src))
#define CP_COMMIT()    asm volatile("cp.async.commit_group;")
#define CP_WAIT0()     asm volatile("cp.async.wait_group 0;" ::: "memory")

// ---------------------------------------------------------------------------
// Prep: W -> hi/lo bf16 planes; zero small accumulators.
__global__ void k_prep(const float* __restrict__ W) {
    int t = blockIdx.x * blockDim.x + threadIdx.x;
    if (t < B_ * K_) { g_ssum[t] = 0.f; g_colss[t] = 0.f; }
    if (t < K_ * D_ / 4) {
        float4 v = *(const float4*)&W[t * 4];
        uint32_t h0, l0, h1, l1;
        split2(v.x, v.y, h0, l0);
        split2(v.z, v.w, h1, l1);
        *(uint2*)&g_Wh[t * 4] = make_uint2(h0, h1);
        *(uint2*)&g_Wl[t * 4] = make_uint2(l0, l1);
    }
}

// ---------------------------------------------------------------------------
// Kernel A: logits[64 k][128 n] = W @ x_tile (reduce D=512), hi/lo 3-pass MMA.
// W planes via cp.async (no conversion); x converted in-regs (cheap split).
// smem: 2 stages of (Wh 5120 | Wl 5120 | Xh 8704 | Xl 8704) = 27648 each.
// post-loop reuse: st f32[64][132] @0 | ssred @33792 | st2h @34048 | st2l @50432
#define PA 40
#define PX 136
#define A_BUF  27648
#define A_ST2H 34048
#define A_ST2L 50432
#define A_SMEM (50432 + 16384)

__global__ __launch_bounds__(256) void kA(const float* __restrict__ x) {
    extern __shared__ char sm[];
    const int b = blockIdx.y, n0 = blockIdx.x * 128;
    const int tid = threadIdx.x, lane = tid & 31, wid = tid >> 5;
    const int wm = wid & 3, wn = wid >> 2;
    const uint32_t smb = smem_u32(sm);

    const int wk2 = tid >> 2, wd8 = (tid & 3) * 8;   // W cp.async: k row, d offset(8)
    const int xnn = lane * 4;                         // x: n offset

    float acc[8][4];
#pragma unroll
    for (int i = 0; i < 8; i++)
#pragma unroll
        for (int j = 0; j < 4; j++) acc[i][j] = 0.f;

    // prologue: issue W chunk 0 via cp.async; prefetch x chunk 0 regs
    {
        uint32_t dst = smb + wk2 * 80 + wd8 * 2;
        CP16(dst,        &g_Wh[wk2 * D_ + wd8]);
        CP16(dst + 5120, &g_Wl[wk2 * D_ + wd8]);
        CP_COMMIT();
    }
    float4 xbuf[4];
#pragma unroll
    for (int p = 0; p < 4; p++)
        xbuf[p] = *(const float4*)&x[((size_t)b * D_ + wid + p * 8) * N_ + n0 + xnn];

    for (int c = 0; c < 16; c++) {
        char* bufc = sm + (c & 1) * A_BUF;
        __nv_bfloat16* Xh = (__nv_bfloat16*)(bufc + 10240);
        __nv_bfloat16* Xl = (__nv_bfloat16*)(bufc + 18944);

        // store x chunk regs -> smem (hi/lo split)
#pragma unroll
        for (int p = 0; p < 4; p++) {
            int dd = wid + p * 8;
            uint32_t h0, l0, h1, l1;
            split2(xbuf[p].x, xbuf[p].y, h0, l0);
            split2(xbuf[p].z, xbuf[p].w, h1, l1);
            int off = dd * PX + xnn;
            *(uint32_t*)&Xh[off] = h0; *(uint32_t*)&Xh[off + 2] = h1;
            *(uint32_t*)&Xl[off] = l0; *(uint32_t*)&Xl[off + 2] = l1;
        }
        CP_WAIT0();
        __syncthreads();

        if (c < 15) {
            int d1 = (c + 1) * 32;
            // issue next W planes into the other stage
            uint32_t dst = smb + ((c + 1) & 1) * A_BUF + wk2 * 80 + wd8 * 2;
            CP16(dst,        &g_Wh[wk2 * D_ + d1 + wd8]);
            CP16(dst + 5120, &g_Wl[wk2 * D_ + d1 + wd8]);
            CP_COMMIT();
            // prefetch next x chunk into regs
#pragma unroll
            for (int p = 0; p < 4; p++)
                xbuf[p] = *(const float4*)&x[((size_t)b * D_ + d1 + wid + p * 8) * N_ + n0 + xnn];
        }

        const uint32_t wh_a = smb + (c & 1) * A_BUF;
        const uint32_t wl_a = wh_a + 5120;
        const uint32_t xh_a = wh_a + 10240;
        const uint32_t xl_a = wh_a + 18944;
#pragma unroll
        for (int ks = 0; ks < 2; ks++) {
            uint32_t ah[4], al[4];
            uint32_t aoff = (uint32_t)(((wm * 16 + (lane & 15)) * PA + ks * 16 + (lane >> 4) * 8) * 2);
            ldsm4(ah, wh_a + aoff);
            ldsm4(al, wl_a + aoff);
#pragma unroll
            for (int nf = 0; nf < 4; nf++) {
                uint32_t bh[4], bl[4];
                uint32_t boff = (uint32_t)(((ks * 16 + (lane & 15)) * PX +
                                            wn * 64 + nf * 16 + (lane >> 4) * 8) * 2);
                ldsm4t(bh, xh_a + boff);
                ldsm4t(bl, xl_a + boff);
                mma_bf16(acc[nf * 2],     ah, bh);
                mma_bf16(acc[nf * 2],     ah, bl);
                mma_bf16(acc[nf * 2],     al, bh);
                mma_bf16(acc[nf * 2 + 1], ah, bh + 2);
                mma_bf16(acc[nf * 2 + 1], ah, bl + 2);
                mma_bf16(acc[nf * 2 + 1], al, bh + 2);
            }
        }
    }
    __syncthreads();

    // stash logits tile [64][132] f32
    float* st = (float*)sm;
    {
        int g = lane >> 2, tg = lane & 3;
        int r0 = wm * 16 + g;
#pragma unroll
        for (int nf = 0; nf < 8; nf++) {
            int cix = wn * 64 + nf * 8 + tg * 2;
            st[r0 * 132 + cix]           = acc[nf][0];
            st[r0 * 132 + cix + 1]       = acc[nf][1];
            st[(r0 + 8) * 132 + cix]     = acc[nf][2];
            st[(r0 + 8) * 132 + cix + 1] = acc[nf][3];
        }
    }
    float* ssred = (float*)(sm + 33792);
    __nv_bfloat16* st2h = (__nv_bfloat16*)(sm + A_ST2H);
    __nv_bfloat16* st2l = (__nv_bfloat16*)(sm + A_ST2L);
    if (tid < 64) ssred[tid] = 0.f;
    __syncthreads();

    // softmax over k per column
    if (tid < 128) {
        int col = tid;
        float m = -1e30f;
#pragma unroll
        for (int k = 0; k < 64; k++) m = fmaxf(m, st[k * 132 + col]);
        float s = 0.f;
#pragma unroll
        for (int k = 0; k < 64; k++) {
            float e = __expf(st[k * 132 + col] - m);
            st[k * 132 + col] = e;
            s += e;
        }
        float inv = 1.f / s;
#pragma unroll
        for (int k = 0; k < 64; k++) {
            float v = st[k * 132 + col] * inv;
            __nv_bfloat16 h = __float2bfloat16(v);
            float r = v - __bfloat162float(h);
            st2h[k * 128 + col] = h;
            st2l[k * 128 + col] = __float2bfloat16(r);
            float ws = v;
#pragma unroll
            for (int o = 16; o > 0; o >>= 1) ws += __shfl_xor_sync(0xffffffff, ws, o);
            if (lane == 0) atomicAdd(&ssred[k], ws);
        }
    }
    __syncthreads();

    // coalesced plane writes: warp w -> rows w*8..w*8+7, uint2 per thread
#pragma unroll
    for (int r = 0; r < 8; r++) {
        int row = wid * 8 + r;
        size_t goff = ((size_t)b * K_ + row) * N_ + n0;
        uint2 vh = ((const uint2*)&st2h[row * 128])[lane];
        uint2 vl = ((const uint2*)&st2l[row * 128])[lane];
        ((uint2*)&g_Sh[goff])[lane] = vh;
        ((uint2*)&g_Sl[goff])[lane] = vl;
    }
    if (tid < 64) atomicAdd(&g_ssum[b * K_ + tid], ssred[tid]);
}

// ---------------------------------------------------------------------------
// Kernel B: agg_part[sp][128 d][64 k] = x_tile @ scores^T (reduce 512 n).
// Score planes via cp.async (no unpack); x converted in-regs.
// smem: 2 stages of (Xh 10240 | Xl 10240 | Sh 5120 | Sl 5120) = 30720 each.
#define PB 40
#define B_BUF  30720
#define B_SMEM (2 * B_BUF)

__global__ __launch_bounds__(256) void kB(const float* __restrict__ x) {
    extern __shared__ char sm[];
    const int b = blockIdx.y;
    const int d0 = (blockIdx.x & 3) * 128;
    const int sp = blockIdx.x >> 2;
    const int spn = sp * 512;
    const int tid = threadIdx.x, lane = tid & 31, wid = tid >> 5;
    const uint32_t smb = smem_u32(sm);

    const int xrr = tid >> 3, xnn = (tid & 7) * 4;   // x: d row base, n offset
    const int sk2 = tid >> 2, sn8 = (tid & 3) * 8;   // S cp.async: k row, n offset(8)

    float acc[8][4];
#pragma unroll
    for (int i = 0; i < 8; i++)
#pragma unroll
        for (int j = 0; j < 4; j++) acc[i][j] = 0.f;

    // prologue: issue S chunk 0; prefetch x chunk 0
    {
        uint32_t dst = smb + 20480 + sk2 * 80 + sn8 * 2;
        size_t gs = ((size_t)b * K_ + sk2) * N_ + spn + sn8;
        CP16(dst,        &g_Sh[gs]);
        CP16(dst + 5120, &g_Sl[gs]);
        CP_COMMIT();
    }
    float4 xbuf[4];
#pragma unroll
    for (int p = 0; p < 4; p++)
        xbuf[p] = *(const float4*)&x[((size_t)b * D_ + d0 + xrr + p * 32) * N_ + spn + xnn];

    for (int c = 0; c < 16; c++) {
        char* bufc = sm + (c & 1) * B_BUF;
        __nv_bfloat16* Xh = (__nv_bfloat16*)(bufc);
        __nv_bfloat16* Xl = (__nv_bfloat16*)(bufc + 10240);

#pragma unroll
        for (int p = 0; p < 4; p++) {
            int rr = xrr + p * 32;
            uint32_t h0, l0, h1, l1;
            split2(xbuf[p].x, xbuf[p].y, h0, l0);
            split2(xbuf[p].z, xbuf[p].w, h1, l1);
            int off = rr * PB + xnn;
            *(uint32_t*)&Xh[off] = h0; *(uint32_t*)&Xh[off + 2] = h1;
            *(uint32_t*)&Xl[off] = l0; *(uint32_t*)&Xl[off + 2] = l1;
        }
        CP_WAIT0();
        __syncthreads();

        if (c < 15) {
            int n1 = spn + (c + 1) * 32;
            uint32_t dst = smb + ((c + 1) & 1) * B_BUF + 20480 + sk2 * 80 + sn8 * 2;
            size_t gs = ((size_t)b * K_ + sk2) * N_ + n1 + sn8;
            CP16(dst,        &g_Sh[gs]);
            CP16(dst + 5120, &g_Sl[gs]);
            CP_COMMIT();
#pragma unroll
            for (int p = 0; p < 4; p++)
                xbuf[p] = *(const float4*)&x[((size_t)b * D_ + d0 + xrr + p * 32) * N_ + n1 + xnn];
        }

        const uint32_t xh_a = smb + (c & 1) * B_BUF;
        const uint32_t xl_a = xh_a + 10240;
        const uint32_t sh_a = xh_a + 20480;
        const uint32_t sl_a = xh_a + 25600;
#pragma unroll
        for (int ks = 0; ks < 2; ks++) {
            uint32_t ah[4], al[4];
            uint32_t aoff = (uint32_t)(((wid * 16 + (lane & 15)) * PB + ks * 16 + (lane >> 4) * 8) * 2);
            ldsm4(ah, xh_a + aoff);
            ldsm4(al, xl_a + aoff);
#pragma unroll
            for (int nf = 0; nf < 4; nf++) {
                uint32_t bh[4], bl[4];
                uint32_t boff = (uint32_t)(((nf * 16 + (lane & 7) + ((lane >> 4) << 3)) * PB +
                                            ks * 16 + ((lane >> 3) & 1) * 8) * 2);
                ldsm4(bh, sh_a + boff);
                ldsm4(bl, sl_a + boff);
                mma_bf16(acc[nf * 2],     ah, bh);
                mma_bf16(acc[nf * 2],     ah, bl);
                mma_bf16(acc[nf * 2],     al, bh);
                mma_bf16(acc[nf * 2 + 1], ah, bh + 2);
                mma_bf16(acc[nf * 2 + 1], ah, bl + 2);
                mma_bf16(acc[nf * 2 + 1], al, bh + 2);
            }
        }
    }

    // non-atomic writes into this split's partial buffer
    int g = lane >> 2, tg = lane & 3;
    int d = d0 + wid * 16 + g;
    float* base = &g_aggp[sp][((size_t)b * D_ + d) * K_];
#pragma unroll
    for (int nf = 0; nf < 8; nf++) {
        int cix = nf * 8 + tg * 2;
        base[cix]              = acc[nf][0];
        base[cix + 1]          = acc[nf][1];
        base[8 * K_ + cix]     = acc[nf][2];
        base[8 * K_ + cix + 1] = acc[nf][3];
    }
}

// ---------------------------------------------------------------------------
// Epilogue
__global__ __launch_bounds__(256) void k_colss(const float* __restrict__ centers) {
    const int b = blockIdx.y, d0 = blockIdx.x * 32;
    const int tid = threadIdx.x;
    const int k = tid & 63, dg = tid >> 6;
    __shared__ float red[4][64];
    const float ssumk = g_ssum[b * K_ + k];
    float acc = 0.f;
#pragma unroll
    for (int t = 0; t < 8; t++) {
        int d = d0 + dg + t * 4;
        size_t idx = (size_t)b * D_ * K_ + (size_t)d * K_ + k;
        float v = g_aggp[0][idx] + g_aggp[1][idx] + g_aggp[2][idx] + g_aggp[3][idx]
                  - centers[d * K_ + k] * ssumk;
        g_aggp[0][idx] = v;
        acc = fmaf(v, v, acc);
    }
    red[dg][k] = acc;
    __syncthreads();
    if (tid < 64) {
        float tot = red[0][tid] + red[1][tid] + red[2][tid] + red[3][tid];
        atomicAdd(&g_colss[b * K_ + tid], tot);
    }
}

__global__ void k_mult() {
    const int b = blockIdx.x, k = threadIdx.x;
    __shared__ float sh[64];
    float ss = g_colss[b * K_ + k];
    float m = fmaxf(sqrtf(ss), 1e-12f);
    sh[k] = ss / (m * m);
    __syncthreads();
    for (int o = 32; o > 0; o >>= 1) {
        if (k < o) sh[k] += sh[k + o];
        __syncthreads();
    }
    float scale2 = 1.f / fmaxf(sqrtf(sh[0]), 1e-12f);
    g_mult[b * K_ + k] = scale2 / m;
}

__global__ __launch_bounds__(256) void k_out(float* __restrict__ out) {
    const int b = blockIdx.y, d0 = blockIdx.x * 32;
    const int tid = threadIdx.x;
    const int k = tid & 63, dg = tid >> 6;
    const float mult = g_mult[b * K_ + k];
    float* op = &out[(size_t)b * D_ * K_];
#pragma unroll
    for (int t = 0; t < 8; t++) {
        int d = d0 + dg + t * 4;
        size_t idx = (size_t)b * D_ * K_ + (size_t)d * K_ + k;
        op[d * K_ + k] = g_aggp[0][idx] * mult;
    }
}

// ---------------------------------------------------------------------------
extern "C" void kernel_launch(void* const* d_in, const int* in_sizes, int n_in,
                              void* d_out, int out_size) {
    const float* x       = (const float*)d_in[0];  // [B, D, N]
    const float* W       = (const float*)d_in[1];  // [K, D]
    const float* centers = (const float*)d_in[2];  // [D, K]
    float* out = (float*)d_out;                    // [B, D*K]

    cudaFuncSetAttribute(kA, cudaFuncAttributeMaxDynamicSharedMemorySize, A_SMEM);
    cudaFuncSetAttribute(kB, cudaFuncAttributeMaxDynamicSharedMemorySize, B_SMEM);

    k_prep<<<32, 256>>>(W);
    dim3 gA(N_ / 128, B_);
    kA<<<gA, 256, A_SMEM>>>(x);
    dim3 gB(16, B_);           // 4 d-tiles x 4 n-splits
    kB<<<gB, 256, B_SMEM>>>(x);
    dim3 gE(D_ / 32, B_);
    k_colss<<<gE, 256>>>(centers);
    k_mult<<<B_, 64>>>();
    k_out<<<gE, 256>>>(out);
}